// round 9
// baseline (speedup 1.0000x reference)
#include <cuda_runtime.h>

#define N_NODES   100000
#define N_EDGES   600000
#define D_FEAT    128
#define N_CLASSES 40
#define NB_SCAN   391        // ceil(N_NODES / 256)
#define CHUNK     8          // gathers kept in flight per agg iteration

// Scratch (allocation-free rule: __device__ globals).
__device__ float g_bufA[(size_t)N_NODES * D_FEAT];
__device__ float g_bufB[(size_t)N_NODES * D_FEAT];
__device__ int   g_deg[N_NODES];
__device__ float g_dinv[N_NODES];
__device__ int   g_rowstart[N_NODES];
__device__ int   g_cursor[N_NODES];
__device__ int   g_csr[N_EDGES];        // src ids grouped by dst
__device__ int   g_blocksum[NB_SCAN];
__device__ int   g_blockoff[NB_SCAN];
__device__ unsigned g_fmt;              // 0 -> edge_index int64, else int32

// ---- init: zero deg, reset dtype probe ------------------------------------
__global__ void k_init() {
    int i = blockIdx.x * blockDim.x + threadIdx.x;
    if (i == 0) g_fmt = 0u;
    if (i < N_NODES) g_deg[i] = 0;
}

// dtype probe: OR all odd int32 words. int64 node ids (<1e5) have zero high
// halves -> OR==0; int32 layout puts random ids there -> OR!=0.
__global__ void k_probe(const int* __restrict__ e32) {
    int i = blockIdx.x * blockDim.x + threadIdx.x;
    unsigned v = 0;
    if (i < N_EDGES) v = (unsigned)e32[2 * i + 1];
    #pragma unroll
    for (int off = 16; off; off >>= 1)
        v |= __shfl_xor_sync(0xffffffffu, v, off);
    if ((threadIdx.x & 31) == 0 && v) atomicOr(&g_fmt, v);
}

__device__ __forceinline__ void decode_edge(const int* __restrict__ e32,
                                            int e, int& s, int& d) {
    if (g_fmt) { s = e32[e];     d = e32[N_EDGES + e]; }
    else       { s = e32[2 * e]; d = e32[2 * (N_EDGES + e)]; }
    if ((unsigned)s >= N_NODES) s = 0;   // defensive: soft-fail, no trap
    if ((unsigned)d >= N_NODES) d = 0;
}

// count in-degree (decode on the fly)
__global__ void k_count(const int* __restrict__ e32) {
    int e = blockIdx.x * blockDim.x + threadIdx.x;
    if (e >= N_EDGES) return;
    int s, d;
    decode_edge(e32, e, s, d);
    atomicAdd(&g_deg[d], 1);
}

// ---- block scan of deg (+ fused dinv computation) -------------------------
__global__ void k_block_scan() {
    int tid = threadIdx.x, lane = tid & 31, warp = tid >> 5;
    int i = blockIdx.x * 256 + tid;
    int v = (i < N_NODES) ? g_deg[i] : 0;
    if (i < N_NODES) g_dinv[i] = rsqrtf((float)v + 1.0f);   // fused
    int x = v;
    #pragma unroll
    for (int off = 1; off < 32; off <<= 1) {
        int y = __shfl_up_sync(0xffffffffu, x, off);
        if (lane >= off) x += y;
    }
    __shared__ int wsum[8];
    if (lane == 31) wsum[warp] = x;
    __syncthreads();
    if (tid < 8) {
        int wv = wsum[tid];
        #pragma unroll
        for (int off = 1; off < 8; off <<= 1) {
            int y = __shfl_up_sync(0xffu, wv, off);
            if (tid >= off) wv += y;
        }
        wsum[tid] = wv;                 // inclusive warp sums
    }
    __syncthreads();
    int base = (warp > 0) ? wsum[warp - 1] : 0;
    int incl = x + base;
    if (i < N_NODES) g_rowstart[i] = incl - v;   // block-local exclusive
    if (tid == 255) g_blocksum[blockIdx.x] = incl;
}

__global__ void k_scan_sums() {       // 1 block, 512 threads; NB_SCAN=391<512
    int tid = threadIdx.x, lane = tid & 31, warp = tid >> 5;
    int v = (tid < NB_SCAN) ? g_blocksum[tid] : 0;
    int x = v;
    #pragma unroll
    for (int off = 1; off < 32; off <<= 1) {
        int y = __shfl_up_sync(0xffffffffu, x, off);
        if (lane >= off) x += y;
    }
    __shared__ int wsum[16];
    if (lane == 31) wsum[warp] = x;
    __syncthreads();
    if (tid < 16) {
        int wv = wsum[tid];
        #pragma unroll
        for (int off = 1; off < 16; off <<= 1) {
            int y = __shfl_up_sync(0xffffu, wv, off);
            if (tid >= off) wv += y;
        }
        wsum[tid] = wv;
    }
    __syncthreads();
    int base = (warp > 0) ? wsum[warp - 1] : 0;
    if (tid < NB_SCAN) g_blockoff[tid] = x + base - v;   // exclusive
}

__global__ void k_finalize() {
    int i = blockIdx.x * blockDim.x + threadIdx.x;
    if (i >= N_NODES) return;
    int rs = g_rowstart[i] + g_blockoff[i >> 8];
    g_rowstart[i] = rs;
    g_cursor[i]   = rs;
}

// ---- bin edges into CSR ---------------------------------------------------
__global__ void k_bin(const int* __restrict__ e32) {
    int e = blockIdx.x * blockDim.x + threadIdx.x;
    if (e >= N_EDGES) return;
    int s, d;
    decode_edge(e32, e, s, d);
    int pos = atomicAdd(&g_cursor[d], 1);
    g_csr[pos] = s;
}

// ---- round 1: bufB = dinv^2 * ( dinv[w]*x[w] + sum dinv[s]*x[s] ) ---------
// (produces u2 directly from raw x; scale_init pass eliminated)
__global__ void k_agg1(const float4* __restrict__ x) {
    int w    = (blockIdx.x * blockDim.x + threadIdx.x) >> 5;
    int lane = threadIdx.x & 31;
    if (w >= N_NODES) return;
    int r0 = g_rowstart[w];
    int r1 = r0 + g_deg[w];
    float dv = g_dinv[w];

    float4 acc = x[w * 32 + lane];
    acc.x *= dv; acc.y *= dv; acc.z *= dv; acc.w *= dv;   // self term

    int e = r0;
    while (e < r1) {
        int n = r1 - e; if (n > CHUNK) n = CHUNK;
        int   idx[CHUNK];
        float wt[CHUNK];
        #pragma unroll
        for (int j = 0; j < CHUNK; j++)           // independent broadcast loads
            idx[j] = (j < n) ? g_csr[e + j] : 0;
        #pragma unroll
        for (int j = 0; j < CHUNK; j++)
            wt[j] = (j < n) ? g_dinv[idx[j]] : 0.0f;
        float4 v[CHUNK];
        #pragma unroll
        for (int j = 0; j < CHUNK; j++)           // all gathers in flight
            if (j < n) v[j] = x[idx[j] * 32 + lane];
        #pragma unroll
        for (int j = 0; j < CHUNK; j++)
            if (j < n) {
                acc.x = fmaf(wt[j], v[j].x, acc.x);
                acc.y = fmaf(wt[j], v[j].y, acc.y);
                acc.z = fmaf(wt[j], v[j].z, acc.z);
                acc.w = fmaf(wt[j], v[j].w, acc.w);
            }
        e += n;
    }
    float sc = dv * dv;
    acc.x *= sc; acc.y *= sc; acc.z *= sc; acc.w *= sc;
    ((float4*)g_bufB)[w * 32 + lane] = acc;
}

// ---- round 2: bufA = dinv * ( u2[w] + sum u2[s] ) -------------------------
__global__ void k_agg2() {
    const float4* __restrict__ src = (const float4*)g_bufB;
    int w    = (blockIdx.x * blockDim.x + threadIdx.x) >> 5;
    int lane = threadIdx.x & 31;
    if (w >= N_NODES) return;
    int r0 = g_rowstart[w];
    int r1 = r0 + g_deg[w];

    float4 acc = src[w * 32 + lane];              // self term

    int e = r0;
    while (e < r1) {
        int n = r1 - e; if (n > CHUNK) n = CHUNK;
        int idx[CHUNK];
        #pragma unroll
        for (int j = 0; j < CHUNK; j++)
            idx[j] = (j < n) ? g_csr[e + j] : 0;
        float4 v[CHUNK];
        #pragma unroll
        for (int j = 0; j < CHUNK; j++)
            if (j < n) v[j] = src[idx[j] * 32 + lane];
        #pragma unroll
        for (int j = 0; j < CHUNK; j++)
            if (j < n) {
                acc.x += v[j].x; acc.y += v[j].y;
                acc.z += v[j].z; acc.w += v[j].w;
            }
        e += n;
    }
    float dv = g_dinv[w];
    acc.x *= dv; acc.y *= dv; acc.z *= dv; acc.w *= dv;
    ((float4*)g_bufA)[w * 32 + lane] = acc;
}

// ---- classifier: logits = bufA @ W^T + b ; log_softmax --------------------
__global__ void k_classify(const float* __restrict__ W,
                           const float* __restrict__ b,
                           float* __restrict__ out) {
    __shared__ float2 Wp[D_FEAT * 32];
    __shared__ float  bsh[64];
    __shared__ float  xsh[8][D_FEAT];

    for (int idx = threadIdx.x; idx < D_FEAT * 32; idx += blockDim.x) {
        int k = idx >> 5, c = idx & 31;
        float w0 = W[c * D_FEAT + k];
        float w1 = (c + 32 < N_CLASSES) ? W[(c + 32) * D_FEAT + k] : 0.0f;
        Wp[idx] = make_float2(w0, w1);
    }
    if (threadIdx.x < 64)
        bsh[threadIdx.x] = (threadIdx.x < N_CLASSES) ? b[threadIdx.x] : 0.0f;
    __syncthreads();

    int lane   = threadIdx.x & 31;
    int wlocal = threadIdx.x >> 5;
    int gwarp  = blockIdx.x * (blockDim.x >> 5) + wlocal;
    int nwarps = gridDim.x * (blockDim.x >> 5);

    for (int node = gwarp; node < N_NODES; node += nwarps) {
        float4 xv = ((const float4*)g_bufA)[node * 32 + lane];
        ((float4*)xsh[wlocal])[lane] = xv;
        __syncwarp();

        float acc0 = bsh[lane];
        float acc1 = bsh[lane + 32];
        #pragma unroll 8
        for (int k = 0; k < D_FEAT; k++) {
            float xk = xsh[wlocal][k];
            float2 wp = Wp[(k << 5) | lane];
            acc0 = fmaf(xk, wp.x, acc0);
            acc1 = fmaf(xk, wp.y, acc1);
        }

        float v1 = (lane < 8) ? acc1 : -1e30f;
        float m = fmaxf(acc0, v1);
        #pragma unroll
        for (int off = 16; off; off >>= 1)
            m = fmaxf(m, __shfl_xor_sync(0xffffffffu, m, off));
        float s = expf(acc0 - m) + ((lane < 8) ? expf(acc1 - m) : 0.0f);
        #pragma unroll
        for (int off = 16; off; off >>= 1)
            s += __shfl_xor_sync(0xffffffffu, s, off);
        float ls = m + logf(s);

        out[node * N_CLASSES + lane] = acc0 - ls;
        if (lane < 8)
            out[node * N_CLASSES + 32 + lane] = acc1 - ls;
        __syncwarp();
    }
}

extern "C" void kernel_launch(void* const* d_in, const int* in_sizes, int n_in,
                              void* d_out, int out_size) {
    const float* x  = (const float*)d_in[0];
    const int*   ei = (const int*)d_in[1];   // dtype resolved on device (g_fmt)
    const float* W  = (const float*)d_in[2];
    const float* b  = (const float*)d_in[3];
    float* out = (float*)d_out;

    const int T = 256;
    const int nodeBlocks = (N_NODES + T - 1) / T;                 // 391
    const int edgeBlocks = (N_EDGES + T - 1) / T;                 // 2344
    const int aggBlocks  = (N_NODES * 32 + T - 1) / T;            // 12500

    k_init       <<<nodeBlocks, T>>>();
    k_probe      <<<edgeBlocks, T>>>(ei);
    k_count      <<<edgeBlocks, T>>>(ei);
    k_block_scan <<<NB_SCAN,    T>>>();
    k_scan_sums  <<<1,        512>>>();
    k_finalize   <<<nodeBlocks, T>>>();
    k_bin        <<<edgeBlocks, T>>>(ei);
    k_agg1       <<<aggBlocks,  T>>>((const float4*)x);
    k_agg2       <<<aggBlocks,  T>>>();
    k_classify   <<<1184,       T>>>(W, b, out);
}

// round 10
// speedup vs baseline: 1.2062x; 1.2062x over previous
#include <cuda_runtime.h>

#define N_NODES   100000
#define N_EDGES   600000
#define D_FEAT    128
#define N_CLASSES 40
#define NB_SCAN   391        // ceil(N_NODES / 256)

// Scratch (allocation-free rule: __device__ globals).
__device__ float g_bufA[(size_t)N_NODES * D_FEAT];
__device__ float g_bufB[(size_t)N_NODES * D_FEAT];
__device__ int   g_deg[N_NODES];
__device__ float g_dinv[N_NODES];
__device__ int   g_rowstart[N_NODES];
__device__ int   g_cursor[N_NODES];
__device__ int   g_csr[N_EDGES];        // src ids grouped by dst
__device__ int   g_blocksum[NB_SCAN];
__device__ int   g_blockoff[NB_SCAN];
__device__ unsigned g_fmt;              // 0 -> edge_index int64, else int32

// ---- init: zero deg, reset dtype probe ------------------------------------
__global__ void k_init() {
    int i = blockIdx.x * blockDim.x + threadIdx.x;
    if (i == 0) g_fmt = 0u;
    if (i < N_NODES) g_deg[i] = 0;
}

// dtype probe: OR all odd int32 words. int64 node ids (<1e5) have zero high
// halves -> OR==0; int32 layout puts random ids there -> OR!=0.
__global__ void k_probe(const int* __restrict__ e32) {
    int i = blockIdx.x * blockDim.x + threadIdx.x;
    unsigned v = 0;
    if (i < N_EDGES) v = (unsigned)e32[2 * i + 1];
    #pragma unroll
    for (int off = 16; off; off >>= 1)
        v |= __shfl_xor_sync(0xffffffffu, v, off);
    if ((threadIdx.x & 31) == 0 && v) atomicOr(&g_fmt, v);
}

__device__ __forceinline__ void decode_edge(const int* __restrict__ e32,
                                            int e, int& s, int& d) {
    if (g_fmt) { s = e32[e];     d = e32[N_EDGES + e]; }
    else       { s = e32[2 * e]; d = e32[2 * (N_EDGES + e)]; }
    if ((unsigned)s >= N_NODES) s = 0;   // defensive: soft-fail, no trap
    if ((unsigned)d >= N_NODES) d = 0;
}

// count in-degree (decode on the fly)
__global__ void k_count(const int* __restrict__ e32) {
    int e = blockIdx.x * blockDim.x + threadIdx.x;
    if (e >= N_EDGES) return;
    int s, d;
    decode_edge(e32, e, s, d);
    atomicAdd(&g_deg[d], 1);
}

// ---- block scan of deg (+ fused dinv computation) -------------------------
__global__ void k_block_scan() {
    int tid = threadIdx.x, lane = tid & 31, warp = tid >> 5;
    int i = blockIdx.x * 256 + tid;
    int v = (i < N_NODES) ? g_deg[i] : 0;
    if (i < N_NODES) g_dinv[i] = rsqrtf((float)v + 1.0f);   // fused
    int x = v;
    #pragma unroll
    for (int off = 1; off < 32; off <<= 1) {
        int y = __shfl_up_sync(0xffffffffu, x, off);
        if (lane >= off) x += y;
    }
    __shared__ int wsum[8];
    if (lane == 31) wsum[warp] = x;
    __syncthreads();
    if (tid < 8) {
        int wv = wsum[tid];
        #pragma unroll
        for (int off = 1; off < 8; off <<= 1) {
            int y = __shfl_up_sync(0xffu, wv, off);
            if (tid >= off) wv += y;
        }
        wsum[tid] = wv;                 // inclusive warp sums
    }
    __syncthreads();
    int base = (warp > 0) ? wsum[warp - 1] : 0;
    int incl = x + base;
    if (i < N_NODES) g_rowstart[i] = incl - v;   // block-local exclusive
    if (tid == 255) g_blocksum[blockIdx.x] = incl;
}

__global__ void k_scan_sums() {       // 1 block, 512 threads; NB_SCAN=391<512
    int tid = threadIdx.x, lane = tid & 31, warp = tid >> 5;
    int v = (tid < NB_SCAN) ? g_blocksum[tid] : 0;
    int x = v;
    #pragma unroll
    for (int off = 1; off < 32; off <<= 1) {
        int y = __shfl_up_sync(0xffffffffu, x, off);
        if (lane >= off) x += y;
    }
    __shared__ int wsum[16];
    if (lane == 31) wsum[warp] = x;
    __syncthreads();
    if (tid < 16) {
        int wv = wsum[tid];
        #pragma unroll
        for (int off = 1; off < 16; off <<= 1) {
            int y = __shfl_up_sync(0xffffu, wv, off);
            if (tid >= off) wv += y;
        }
        wsum[tid] = wv;
    }
    __syncthreads();
    int base = (warp > 0) ? wsum[warp - 1] : 0;
    if (tid < NB_SCAN) g_blockoff[tid] = x + base - v;   // exclusive
}

__global__ void k_finalize() {
    int i = blockIdx.x * blockDim.x + threadIdx.x;
    if (i >= N_NODES) return;
    int rs = g_rowstart[i] + g_blockoff[i >> 8];
    g_rowstart[i] = rs;
    g_cursor[i]   = rs;
}

// ---- bin edges into CSR ---------------------------------------------------
__global__ void k_bin(const int* __restrict__ e32) {
    int e = blockIdx.x * blockDim.x + threadIdx.x;
    if (e >= N_EDGES) return;
    int s, d;
    decode_edge(e32, e, s, d);
    int pos = atomicAdd(&g_cursor[d], 1);
    g_csr[pos] = s;
}

// ---- round 1: bufB = dinv^2 * ( dinv[w]*x[w] + sum dinv[s]*x[s] ) ---------
// Straight-line 4/2/1 unroll: up to 4 independent 512B gathers in flight,
// no predicated register arrays (the CHUNK=8 version spilled / regressed).
__global__ void k_agg1(const float4* __restrict__ x) {
    int w    = (blockIdx.x * blockDim.x + threadIdx.x) >> 5;
    int lane = threadIdx.x & 31;
    if (w >= N_NODES) return;
    int r0 = g_rowstart[w];
    int r1 = r0 + g_deg[w];
    float dv = g_dinv[w];

    float4 acc = x[w * 32 + lane];
    acc.x *= dv; acc.y *= dv; acc.z *= dv; acc.w *= dv;   // self term

    int e = r0;
    for (; e + 4 <= r1; e += 4) {
        int i0 = g_csr[e],     i1 = g_csr[e + 1];
        int i2 = g_csr[e + 2], i3 = g_csr[e + 3];
        float w0 = g_dinv[i0], w1 = g_dinv[i1];
        float w2 = g_dinv[i2], w3 = g_dinv[i3];
        float4 a = x[i0 * 32 + lane];
        float4 b = x[i1 * 32 + lane];
        float4 c = x[i2 * 32 + lane];
        float4 d = x[i3 * 32 + lane];
        acc.x = fmaf(w0, a.x, acc.x); acc.y = fmaf(w0, a.y, acc.y);
        acc.z = fmaf(w0, a.z, acc.z); acc.w = fmaf(w0, a.w, acc.w);
        acc.x = fmaf(w1, b.x, acc.x); acc.y = fmaf(w1, b.y, acc.y);
        acc.z = fmaf(w1, b.z, acc.z); acc.w = fmaf(w1, b.w, acc.w);
        acc.x = fmaf(w2, c.x, acc.x); acc.y = fmaf(w2, c.y, acc.y);
        acc.z = fmaf(w2, c.z, acc.z); acc.w = fmaf(w2, c.w, acc.w);
        acc.x = fmaf(w3, d.x, acc.x); acc.y = fmaf(w3, d.y, acc.y);
        acc.z = fmaf(w3, d.z, acc.z); acc.w = fmaf(w3, d.w, acc.w);
    }
    if (e + 2 <= r1) {
        int i0 = g_csr[e], i1 = g_csr[e + 1];
        float w0 = g_dinv[i0], w1 = g_dinv[i1];
        float4 a = x[i0 * 32 + lane];
        float4 b = x[i1 * 32 + lane];
        acc.x = fmaf(w0, a.x, acc.x); acc.y = fmaf(w0, a.y, acc.y);
        acc.z = fmaf(w0, a.z, acc.z); acc.w = fmaf(w0, a.w, acc.w);
        acc.x = fmaf(w1, b.x, acc.x); acc.y = fmaf(w1, b.y, acc.y);
        acc.z = fmaf(w1, b.z, acc.z); acc.w = fmaf(w1, b.w, acc.w);
        e += 2;
    }
    if (e < r1) {
        int i0 = g_csr[e];
        float w0 = g_dinv[i0];
        float4 a = x[i0 * 32 + lane];
        acc.x = fmaf(w0, a.x, acc.x); acc.y = fmaf(w0, a.y, acc.y);
        acc.z = fmaf(w0, a.z, acc.z); acc.w = fmaf(w0, a.w, acc.w);
    }
    float sc = dv * dv;
    acc.x *= sc; acc.y *= sc; acc.z *= sc; acc.w *= sc;
    ((float4*)g_bufB)[w * 32 + lane] = acc;
}

// ---- round 2: bufA = dinv * ( u2[w] + sum u2[s] ) -------------------------
__global__ void k_agg2() {
    const float4* __restrict__ src = (const float4*)g_bufB;
    int w    = (blockIdx.x * blockDim.x + threadIdx.x) >> 5;
    int lane = threadIdx.x & 31;
    if (w >= N_NODES) return;
    int r0 = g_rowstart[w];
    int r1 = r0 + g_deg[w];

    float4 acc = src[w * 32 + lane];              // self term

    int e = r0;
    for (; e + 4 <= r1; e += 4) {
        int i0 = g_csr[e],     i1 = g_csr[e + 1];
        int i2 = g_csr[e + 2], i3 = g_csr[e + 3];
        float4 a = src[i0 * 32 + lane];
        float4 b = src[i1 * 32 + lane];
        float4 c = src[i2 * 32 + lane];
        float4 d = src[i3 * 32 + lane];
        acc.x += a.x + b.x + c.x + d.x;
        acc.y += a.y + b.y + c.y + d.y;
        acc.z += a.z + b.z + c.z + d.z;
        acc.w += a.w + b.w + c.w + d.w;
    }
    if (e + 2 <= r1) {
        int i0 = g_csr[e], i1 = g_csr[e + 1];
        float4 a = src[i0 * 32 + lane];
        float4 b = src[i1 * 32 + lane];
        acc.x += a.x + b.x; acc.y += a.y + b.y;
        acc.z += a.z + b.z; acc.w += a.w + b.w;
        e += 2;
    }
    if (e < r1) {
        float4 a = src[g_csr[e] * 32 + lane];
        acc.x += a.x; acc.y += a.y; acc.z += a.z; acc.w += a.w;
    }
    float dv = g_dinv[w];
    acc.x *= dv; acc.y *= dv; acc.z *= dv; acc.w *= dv;
    ((float4*)g_bufA)[w * 32 + lane] = acc;
}

// ---- classifier: logits = bufA @ W^T + b ; log_softmax --------------------
__global__ void k_classify(const float* __restrict__ W,
                           const float* __restrict__ b,
                           float* __restrict__ out) {
    __shared__ float2 Wp[D_FEAT * 32];
    __shared__ float  bsh[64];
    __shared__ float  xsh[8][D_FEAT];

    for (int idx = threadIdx.x; idx < D_FEAT * 32; idx += blockDim.x) {
        int k = idx >> 5, c = idx & 31;
        float w0 = W[c * D_FEAT + k];
        float w1 = (c + 32 < N_CLASSES) ? W[(c + 32) * D_FEAT + k] : 0.0f;
        Wp[idx] = make_float2(w0, w1);
    }
    if (threadIdx.x < 64)
        bsh[threadIdx.x] = (threadIdx.x < N_CLASSES) ? b[threadIdx.x] : 0.0f;
    __syncthreads();

    int lane   = threadIdx.x & 31;
    int wlocal = threadIdx.x >> 5;
    int gwarp  = blockIdx.x * (blockDim.x >> 5) + wlocal;
    int nwarps = gridDim.x * (blockDim.x >> 5);

    for (int node = gwarp; node < N_NODES; node += nwarps) {
        float4 xv = ((const float4*)g_bufA)[node * 32 + lane];
        ((float4*)xsh[wlocal])[lane] = xv;
        __syncwarp();

        float acc0 = bsh[lane];
        float acc1 = bsh[lane + 32];
        #pragma unroll 8
        for (int k = 0; k < D_FEAT; k++) {
            float xk = xsh[wlocal][k];
            float2 wp = Wp[(k << 5) | lane];
            acc0 = fmaf(xk, wp.x, acc0);
            acc1 = fmaf(xk, wp.y, acc1);
        }

        float v1 = (lane < 8) ? acc1 : -1e30f;
        float m = fmaxf(acc0, v1);
        #pragma unroll
        for (int off = 16; off; off >>= 1)
            m = fmaxf(m, __shfl_xor_sync(0xffffffffu, m, off));
        float s = expf(acc0 - m) + ((lane < 8) ? expf(acc1 - m) : 0.0f);
        #pragma unroll
        for (int off = 16; off; off >>= 1)
            s += __shfl_xor_sync(0xffffffffu, s, off);
        float ls = m + logf(s);

        out[node * N_CLASSES + lane] = acc0 - ls;
        if (lane < 8)
            out[node * N_CLASSES + 32 + lane] = acc1 - ls;
        __syncwarp();
    }
}

extern "C" void kernel_launch(void* const* d_in, const int* in_sizes, int n_in,
                              void* d_out, int out_size) {
    const float* x  = (const float*)d_in[0];
    const int*   ei = (const int*)d_in[1];   // dtype resolved on device (g_fmt)
    const float* W  = (const float*)d_in[2];
    const float* b  = (const float*)d_in[3];
    float* out = (float*)d_out;

    const int T = 256;
    const int nodeBlocks = (N_NODES + T - 1) / T;                 // 391
    const int edgeBlocks = (N_EDGES + T - 1) / T;                 // 2344
    const int aggBlocks  = (N_NODES * 32 + T - 1) / T;            // 12500

    k_init       <<<nodeBlocks, T>>>();
    k_probe      <<<edgeBlocks, T>>>(ei);
    k_count      <<<edgeBlocks, T>>>(ei);
    k_block_scan <<<NB_SCAN,    T>>>();
    k_scan_sums  <<<1,        512>>>();
    k_finalize   <<<nodeBlocks, T>>>();
    k_bin        <<<edgeBlocks, T>>>(ei);
    k_agg1       <<<aggBlocks,  T>>>((const float4*)x);
    k_agg2       <<<aggBlocks,  T>>>();
    k_classify   <<<1184,       T>>>(W, b, out);
}

// round 11
// speedup vs baseline: 1.7505x; 1.4513x over previous
#include <cuda_runtime.h>

#define N_NODES   100000
#define N_EDGES   600000
#define D_FEAT    128
#define N_CLASSES 40
#define NB_SCAN   391        // ceil(N_NODES / 256)

// Scratch (allocation-free rule: __device__ globals).
__device__ float g_bufA[(size_t)N_NODES * D_FEAT];
__device__ float g_bufB[(size_t)N_NODES * D_FEAT];
__device__ int   g_deg[N_NODES];
__device__ float g_dinv[N_NODES];
__device__ int   g_rowstart[N_NODES];
__device__ int   g_cursor[N_NODES];
__device__ int   g_csr[N_EDGES];        // src ids grouped by dst
__device__ int   g_blocksum[NB_SCAN];
__device__ int   g_blockoff[NB_SCAN];
__device__ float g_Wt[D_FEAT * 64];     // transposed W, padded: Wt[k*64+c]
__device__ unsigned g_fmt;              // 0 -> edge_index int64, else int32

// packed f32x2 helpers (Blackwell sm_100+)
#define FMA_F32X2(d, a, b) \
    asm("fma.rn.f32x2 %0, %1, %2, %3;" : "=l"(d) : "l"(a), "l"(b), "l"(d))
#define PACK2(out, v) \
    asm("mov.b64 %0, {%1, %2};" : "=l"(out) : "f"(v), "f"(v))
#define UNPACK2(lo, hi, in) \
    asm("mov.b64 {%0, %1}, %2;" : "=f"(lo), "=f"(hi) : "l"(in))

// ---- init: zero deg, reset probe, build transposed W ----------------------
__global__ void k_init(const float* __restrict__ W) {
    int i = blockIdx.x * blockDim.x + threadIdx.x;
    if (i == 0) g_fmt = 0u;
    if (i < N_NODES) g_deg[i] = 0;
    if (i < D_FEAT * 64) {
        int c = i & 63, k = i >> 6;
        g_Wt[i] = (c < N_CLASSES) ? W[c * D_FEAT + k] : 0.0f;
    }
}

// dtype probe: OR all odd int32 words. int64 node ids (<1e5) have zero high
// halves -> OR==0; int32 layout puts random ids there -> OR!=0.
__global__ void k_probe(const int* __restrict__ e32) {
    int i = blockIdx.x * blockDim.x + threadIdx.x;
    unsigned v = 0;
    if (i < N_EDGES) v = (unsigned)e32[2 * i + 1];
    #pragma unroll
    for (int off = 16; off; off >>= 1)
        v |= __shfl_xor_sync(0xffffffffu, v, off);
    if ((threadIdx.x & 31) == 0 && v) atomicOr(&g_fmt, v);
}

__device__ __forceinline__ void decode_edge(const int* __restrict__ e32,
                                            int e, int& s, int& d) {
    if (g_fmt) { s = e32[e];     d = e32[N_EDGES + e]; }
    else       { s = e32[2 * e]; d = e32[2 * (N_EDGES + e)]; }
    if ((unsigned)s >= N_NODES) s = 0;   // defensive: soft-fail, no trap
    if ((unsigned)d >= N_NODES) d = 0;
}

__global__ void k_count(const int* __restrict__ e32) {
    int e = blockIdx.x * blockDim.x + threadIdx.x;
    if (e >= N_EDGES) return;
    int s, d;
    decode_edge(e32, e, s, d);
    atomicAdd(&g_deg[d], 1);
}

// ---- block scan of deg (+ fused dinv computation) -------------------------
__global__ void k_block_scan() {
    int tid = threadIdx.x, lane = tid & 31, warp = tid >> 5;
    int i = blockIdx.x * 256 + tid;
    int v = (i < N_NODES) ? g_deg[i] : 0;
    if (i < N_NODES) g_dinv[i] = rsqrtf((float)v + 1.0f);   // fused
    int x = v;
    #pragma unroll
    for (int off = 1; off < 32; off <<= 1) {
        int y = __shfl_up_sync(0xffffffffu, x, off);
        if (lane >= off) x += y;
    }
    __shared__ int wsum[8];
    if (lane == 31) wsum[warp] = x;
    __syncthreads();
    if (tid < 8) {
        int wv = wsum[tid];
        #pragma unroll
        for (int off = 1; off < 8; off <<= 1) {
            int y = __shfl_up_sync(0xffu, wv, off);
            if (tid >= off) wv += y;
        }
        wsum[tid] = wv;                 // inclusive warp sums
    }
    __syncthreads();
    int base = (warp > 0) ? wsum[warp - 1] : 0;
    int incl = x + base;
    if (i < N_NODES) g_rowstart[i] = incl - v;   // block-local exclusive
    if (tid == 255) g_blocksum[blockIdx.x] = incl;
}

__global__ void k_scan_sums() {       // 1 block, 512 threads; NB_SCAN=391<512
    int tid = threadIdx.x, lane = tid & 31, warp = tid >> 5;
    int v = (tid < NB_SCAN) ? g_blocksum[tid] : 0;
    int x = v;
    #pragma unroll
    for (int off = 1; off < 32; off <<= 1) {
        int y = __shfl_up_sync(0xffffffffu, x, off);
        if (lane >= off) x += y;
    }
    __shared__ int wsum[16];
    if (lane == 31) wsum[warp] = x;
    __syncthreads();
    if (tid < 16) {
        int wv = wsum[tid];
        #pragma unroll
        for (int off = 1; off < 16; off <<= 1) {
            int y = __shfl_up_sync(0xffffu, wv, off);
            if (tid >= off) wv += y;
        }
        wsum[tid] = wv;
    }
    __syncthreads();
    int base = (warp > 0) ? wsum[warp - 1] : 0;
    if (tid < NB_SCAN) g_blockoff[tid] = x + base - v;   // exclusive
}

__global__ void k_finalize() {
    int i = blockIdx.x * blockDim.x + threadIdx.x;
    if (i >= N_NODES) return;
    int rs = g_rowstart[i] + g_blockoff[i >> 8];
    g_rowstart[i] = rs;
    g_cursor[i]   = rs;
}

__global__ void k_bin(const int* __restrict__ e32) {
    int e = blockIdx.x * blockDim.x + threadIdx.x;
    if (e >= N_EDGES) return;
    int s, d;
    decode_edge(e32, e, s, d);
    int pos = atomicAdd(&g_cursor[d], 1);
    g_csr[pos] = s;
}

// ---- round 1: bufB = dinv^2 * ( dinv[w]*x[w] + sum dinv[s]*x[s] ) ---------
__global__ void k_agg1(const float4* __restrict__ x) {
    int w    = (blockIdx.x * blockDim.x + threadIdx.x) >> 5;
    int lane = threadIdx.x & 31;
    if (w >= N_NODES) return;
    int r0 = g_rowstart[w];
    int r1 = r0 + g_deg[w];
    float dv = g_dinv[w];

    float4 acc = x[w * 32 + lane];
    acc.x *= dv; acc.y *= dv; acc.z *= dv; acc.w *= dv;   // self term

    int e = r0;
    for (; e + 4 <= r1; e += 4) {
        int i0 = g_csr[e],     i1 = g_csr[e + 1];
        int i2 = g_csr[e + 2], i3 = g_csr[e + 3];
        float w0 = g_dinv[i0], w1 = g_dinv[i1];
        float w2 = g_dinv[i2], w3 = g_dinv[i3];
        float4 a = x[i0 * 32 + lane];
        float4 b = x[i1 * 32 + lane];
        float4 c = x[i2 * 32 + lane];
        float4 d = x[i3 * 32 + lane];
        acc.x = fmaf(w0, a.x, acc.x); acc.y = fmaf(w0, a.y, acc.y);
        acc.z = fmaf(w0, a.z, acc.z); acc.w = fmaf(w0, a.w, acc.w);
        acc.x = fmaf(w1, b.x, acc.x); acc.y = fmaf(w1, b.y, acc.y);
        acc.z = fmaf(w1, b.z, acc.z); acc.w = fmaf(w1, b.w, acc.w);
        acc.x = fmaf(w2, c.x, acc.x); acc.y = fmaf(w2, c.y, acc.y);
        acc.z = fmaf(w2, c.z, acc.z); acc.w = fmaf(w2, c.w, acc.w);
        acc.x = fmaf(w3, d.x, acc.x); acc.y = fmaf(w3, d.y, acc.y);
        acc.z = fmaf(w3, d.z, acc.z); acc.w = fmaf(w3, d.w, acc.w);
    }
    if (e + 2 <= r1) {
        int i0 = g_csr[e], i1 = g_csr[e + 1];
        float w0 = g_dinv[i0], w1 = g_dinv[i1];
        float4 a = x[i0 * 32 + lane];
        float4 b = x[i1 * 32 + lane];
        acc.x = fmaf(w0, a.x, acc.x); acc.y = fmaf(w0, a.y, acc.y);
        acc.z = fmaf(w0, a.z, acc.z); acc.w = fmaf(w0, a.w, acc.w);
        acc.x = fmaf(w1, b.x, acc.x); acc.y = fmaf(w1, b.y, acc.y);
        acc.z = fmaf(w1, b.z, acc.z); acc.w = fmaf(w1, b.w, acc.w);
        e += 2;
    }
    if (e < r1) {
        int i0 = g_csr[e];
        float w0 = g_dinv[i0];
        float4 a = x[i0 * 32 + lane];
        acc.x = fmaf(w0, a.x, acc.x); acc.y = fmaf(w0, a.y, acc.y);
        acc.z = fmaf(w0, a.z, acc.z); acc.w = fmaf(w0, a.w, acc.w);
    }
    float sc = dv * dv;
    acc.x *= sc; acc.y *= sc; acc.z *= sc; acc.w *= sc;
    ((float4*)g_bufB)[w * 32 + lane] = acc;
}

// ---- round 2: bufA = dinv * ( u2[w] + sum u2[s] ) -------------------------
__global__ void k_agg2() {
    const float4* __restrict__ src = (const float4*)g_bufB;
    int w    = (blockIdx.x * blockDim.x + threadIdx.x) >> 5;
    int lane = threadIdx.x & 31;
    if (w >= N_NODES) return;
    int r0 = g_rowstart[w];
    int r1 = r0 + g_deg[w];

    float4 acc = src[w * 32 + lane];              // self term

    int e = r0;
    for (; e + 4 <= r1; e += 4) {
        int i0 = g_csr[e],     i1 = g_csr[e + 1];
        int i2 = g_csr[e + 2], i3 = g_csr[e + 3];
        float4 a = src[i0 * 32 + lane];
        float4 b = src[i1 * 32 + lane];
        float4 c = src[i2 * 32 + lane];
        float4 d = src[i3 * 32 + lane];
        acc.x += a.x + b.x + c.x + d.x;
        acc.y += a.y + b.y + c.y + d.y;
        acc.z += a.z + b.z + c.z + d.z;
        acc.w += a.w + b.w + c.w + d.w;
    }
    if (e + 2 <= r1) {
        int i0 = g_csr[e], i1 = g_csr[e + 1];
        float4 a = src[i0 * 32 + lane];
        float4 b = src[i1 * 32 + lane];
        acc.x += a.x + b.x; acc.y += a.y + b.y;
        acc.z += a.z + b.z; acc.w += a.w + b.w;
        e += 2;
    }
    if (e < r1) {
        float4 a = src[g_csr[e] * 32 + lane];
        acc.x += a.x; acc.y += a.y; acc.z += a.z; acc.w += a.w;
    }
    float dv = g_dinv[w];
    acc.x *= dv; acc.y *= dv; acc.z *= dv; acc.w *= dv;
    ((float4*)g_bufA)[w * 32 + lane] = acc;
}

// ---- classifier v2: 8 nodes/warp, transposed Wt from L1, f32x2 FMA --------
// logits[c] = bufA_row . Wt[:,c] + b[c]; then log_softmax over 40 classes.
__global__ void k_classify(const float* __restrict__ b,
                           float* __restrict__ out) {
    __shared__ float xsh[8][D_FEAT * 8];    // [warp][k*8 + node] = 32 KB

    int lane   = threadIdx.x & 31;
    int wl     = threadIdx.x >> 5;
    int gwarp  = blockIdx.x * 8 + wl;
    int nwarps = gridDim.x * 8;

    float b0 = b[lane];                     // class = lane (0..31)
    float b1 = b[32 + (lane & 7)];          // class = 32..39 (dup on hi lanes)

    const float4* __restrict__ xa = (const float4*)g_bufA;

    for (int base = gwarp * 8; base < N_NODES; base += nwarps * 8) {
        // Load 8 node rows, transposed into xsh[k][r].
        // lane handles node r = lane>>2, float4 chunk c = (lane&3)+4i.
        int r = lane >> 2;
        #pragma unroll
        for (int i = 0; i < 8; i++) {
            int c = (lane & 3) + 4 * i;
            float4 v = xa[(base + r) * 32 + c];
            float vv[4] = {v.x, v.y, v.z, v.w};
            #pragma unroll
            for (int j = 0; j < 4; j++)
                xsh[wl][(4 * c + j) * 8 + r] = vv[j];
        }
        __syncwarp();

        // accumulate: acc0[p] = classes c=lane, node pair (2p,2p+1)
        //             acc1[p] = classes c=32+(lane&7)
        unsigned long long a00, a01, a02, a03, a10, a11, a12, a13;
        PACK2(a00, b0); a01 = a00; a02 = a00; a03 = a00;
        PACK2(a10, b1); a11 = a10; a12 = a10; a13 = a10;

        #pragma unroll 4
        for (int k = 0; k < D_FEAT; k++) {
            float wa = g_Wt[k * 64 + lane];
            float wb = g_Wt[k * 64 + 32 + (lane & 7)];
            unsigned long long wa2, wb2;
            PACK2(wa2, wa);
            PACK2(wb2, wb);
            ulonglong2 x01 = *(const ulonglong2*)&xsh[wl][k * 8];      // n0..3
            ulonglong2 x23 = *(const ulonglong2*)&xsh[wl][k * 8 + 4];  // n4..7
            FMA_F32X2(a00, wa2, x01.x); FMA_F32X2(a01, wa2, x01.y);
            FMA_F32X2(a02, wa2, x23.x); FMA_F32X2(a03, wa2, x23.y);
            FMA_F32X2(a10, wb2, x01.x); FMA_F32X2(a11, wb2, x01.y);
            FMA_F32X2(a12, wb2, x23.x); FMA_F32X2(a13, wb2, x23.y);
        }

        unsigned long long p0[4] = {a00, a01, a02, a03};
        unsigned long long p1[4] = {a10, a11, a12, a13};
        #pragma unroll
        for (int rr = 0; rr < 8; rr++) {
            float l0a, l0b, l1a, l1b;
            UNPACK2(l0a, l0b, p0[rr >> 1]);
            UNPACK2(l1a, l1b, p1[rr >> 1]);
            float acc0 = (rr & 1) ? l0b : l0a;
            float acc1 = (rr & 1) ? l1b : l1a;

            float v1 = (lane < 8) ? acc1 : -1e30f;
            float m = fmaxf(acc0, v1);
            #pragma unroll
            for (int off = 16; off; off >>= 1)
                m = fmaxf(m, __shfl_xor_sync(0xffffffffu, m, off));
            float s = expf(acc0 - m) + ((lane < 8) ? expf(acc1 - m) : 0.0f);
            #pragma unroll
            for (int off = 16; off; off >>= 1)
                s += __shfl_xor_sync(0xffffffffu, s, off);
            float ls = m + logf(s);

            int node = base + rr;
            out[node * N_CLASSES + lane] = acc0 - ls;
            if (lane < 8)
                out[node * N_CLASSES + 32 + lane] = acc1 - ls;
        }
        __syncwarp();
    }
}

extern "C" void kernel_launch(void* const* d_in, const int* in_sizes, int n_in,
                              void* d_out, int out_size) {
    const float* x  = (const float*)d_in[0];
    const int*   ei = (const int*)d_in[1];   // dtype resolved on device (g_fmt)
    const float* W  = (const float*)d_in[2];
    const float* b  = (const float*)d_in[3];
    float* out = (float*)d_out;

    const int T = 256;
    const int nodeBlocks = (N_NODES + T - 1) / T;                 // 391
    const int edgeBlocks = (N_EDGES + T - 1) / T;                 // 2344
    const int aggBlocks  = (N_NODES * 32 + T - 1) / T;            // 12500

    k_init       <<<nodeBlocks, T>>>(W);
    k_probe      <<<edgeBlocks, T>>>(ei);
    k_count      <<<edgeBlocks, T>>>(ei);
    k_block_scan <<<NB_SCAN,    T>>>();
    k_scan_sums  <<<1,        512>>>();
    k_finalize   <<<nodeBlocks, T>>>();
    k_bin        <<<edgeBlocks, T>>>(ei);
    k_agg1       <<<aggBlocks,  T>>>((const float4*)x);
    k_agg2       <<<aggBlocks,  T>>>();
    k_classify   <<<1184,       T>>>(b, out);
}

// round 13
// speedup vs baseline: 2.0581x; 1.1757x over previous
#include <cuda_runtime.h>

#define N_NODES   100000
#define N_EDGES   600000
#define D_FEAT    128
#define N_CLASSES 40
#define NB_SCAN   391        // ceil(N_NODES / 256)

// Scratch (allocation-free rule: __device__ globals).
// 40-dim projected buffers: 16 MB each (vs 51 MB feature buffers before).
__device__ float g_u [(size_t)N_NODES * N_CLASSES];   // dinv * (x @ W^T)
__device__ float g_u2[(size_t)N_NODES * N_CLASSES];   // after round 1
__device__ int   g_deg[N_NODES];
__device__ float g_dinv[N_NODES];
__device__ int   g_rowstart[N_NODES];
__device__ int   g_cursor[N_NODES];
__device__ int   g_csr[N_EDGES];        // src ids grouped by dst
__device__ int   g_blocksum[NB_SCAN];
__device__ int   g_blockoff[NB_SCAN];
__device__ float g_Wt[D_FEAT * 64];     // transposed W, padded: Wt[k*64+c]
__device__ unsigned g_fmt;              // 0 -> edge_index int64, else int32

// packed f32x2 helpers (Blackwell sm_100+)
#define FMA_F32X2(d, a, b) \
    asm("fma.rn.f32x2 %0, %1, %2, %3;" : "=l"(d) : "l"(a), "l"(b), "l"(d))
#define PACK2(out, v) \
    asm("mov.b64 %0, {%1, %2};" : "=l"(out) : "f"(v), "f"(v))
#define UNPACK2(lo, hi, in) \
    asm("mov.b64 {%0, %1}, %2;" : "=f"(lo), "=f"(hi) : "l"(in))

// ---- init: zero deg, reset probe, build transposed W ----------------------
__global__ void k_init(const float* __restrict__ W) {
    int i = blockIdx.x * blockDim.x + threadIdx.x;
    if (i == 0) g_fmt = 0u;
    if (i < N_NODES) g_deg[i] = 0;
    if (i < D_FEAT * 64) {
        int c = i & 63, k = i >> 6;
        g_Wt[i] = (c < N_CLASSES) ? W[c * D_FEAT + k] : 0.0f;
    }
}

// dtype probe: OR all odd int32 words. int64 node ids (<1e5) have zero high
// halves -> OR==0; int32 layout puts random ids there -> OR!=0.
__global__ void k_probe(const int* __restrict__ e32) {
    int i = blockIdx.x * blockDim.x + threadIdx.x;
    unsigned v = 0;
    if (i < N_EDGES) v = (unsigned)e32[2 * i + 1];
    #pragma unroll
    for (int off = 16; off; off >>= 1)
        v |= __shfl_xor_sync(0xffffffffu, v, off);
    if ((threadIdx.x & 31) == 0 && v) atomicOr(&g_fmt, v);
}

__device__ __forceinline__ void decode_edge(const int* __restrict__ e32,
                                            int e, int& s, int& d) {
    if (g_fmt) { s = e32[e];     d = e32[N_EDGES + e]; }
    else       { s = e32[2 * e]; d = e32[2 * (N_EDGES + e)]; }
    if ((unsigned)s >= N_NODES) s = 0;   // defensive: soft-fail, no trap
    if ((unsigned)d >= N_NODES) d = 0;
}

__global__ void k_count(const int* __restrict__ e32) {
    int e = blockIdx.x * blockDim.x + threadIdx.x;
    if (e >= N_EDGES) return;
    int s, d;
    decode_edge(e32, e, s, d);
    atomicAdd(&g_deg[d], 1);
}

// ---- block scan of deg (+ fused dinv computation) -------------------------
__global__ void k_block_scan() {
    int tid = threadIdx.x, lane = tid & 31, warp = tid >> 5;
    int i = blockIdx.x * 256 + tid;
    int v = (i < N_NODES) ? g_deg[i] : 0;
    if (i < N_NODES) g_dinv[i] = rsqrtf((float)v + 1.0f);   // fused
    int x = v;
    #pragma unroll
    for (int off = 1; off < 32; off <<= 1) {
        int y = __shfl_up_sync(0xffffffffu, x, off);
        if (lane >= off) x += y;
    }
    __shared__ int wsum[8];
    if (lane == 31) wsum[warp] = x;
    __syncthreads();
    if (tid < 8) {
        int wv = wsum[tid];
        #pragma unroll
        for (int off = 1; off < 8; off <<= 1) {
            int y = __shfl_up_sync(0xffu, wv, off);
            if (tid >= off) wv += y;
        }
        wsum[tid] = wv;                 // inclusive warp sums
    }
    __syncthreads();
    int base = (warp > 0) ? wsum[warp - 1] : 0;
    int incl = x + base;
    if (i < N_NODES) g_rowstart[i] = incl - v;   // block-local exclusive
    if (tid == 255) g_blocksum[blockIdx.x] = incl;
}

__global__ void k_scan_sums() {       // 1 block, 512 threads; NB_SCAN=391<512
    int tid = threadIdx.x, lane = tid & 31, warp = tid >> 5;
    int v = (tid < NB_SCAN) ? g_blocksum[tid] : 0;
    int x = v;
    #pragma unroll
    for (int off = 1; off < 32; off <<= 1) {
        int y = __shfl_up_sync(0xffffffffu, x, off);
        if (lane >= off) x += y;
    }
    __shared__ int wsum[16];
    if (lane == 31) wsum[warp] = x;
    __syncthreads();
    if (tid < 16) {
        int wv = wsum[tid];
        #pragma unroll
        for (int off = 1; off < 16; off <<= 1) {
            int y = __shfl_up_sync(0xffffu, wv, off);
            if (tid >= off) wv += y;
        }
        wsum[tid] = wv;
    }
    __syncthreads();
    int base = (warp > 0) ? wsum[warp - 1] : 0;
    if (tid < NB_SCAN) g_blockoff[tid] = x + base - v;   // exclusive
}

__global__ void k_finalize() {
    int i = blockIdx.x * blockDim.x + threadIdx.x;
    if (i >= N_NODES) return;
    int rs = g_rowstart[i] + g_blockoff[i >> 8];
    g_rowstart[i] = rs;
    g_cursor[i]   = rs;
}

__global__ void k_bin(const int* __restrict__ e32) {
    int e = blockIdx.x * blockDim.x + threadIdx.x;
    if (e >= N_EDGES) return;
    int s, d;
    decode_edge(e32, e, s, d);
    int pos = atomicAdd(&g_cursor[d], 1);
    g_csr[pos] = s;
}

// ---- gemm: u = dinv * (x @ W^T)  [100k x 40] ------------------------------
// Classifier commutes with propagation (all linear): project FIRST, then
// aggregate 40-dim rows. 8 nodes/warp, transposed Wt (L1), f32x2 FMA.
__global__ void k_gemm(const float4* __restrict__ xa) {
    __shared__ float xsh[8][D_FEAT * 8];    // [warp][k*8 + node] = 32 KB

    int lane   = threadIdx.x & 31;
    int wl     = threadIdx.x >> 5;
    int gwarp  = blockIdx.x * 8 + wl;
    int nwarps = gridDim.x * 8;

    for (int base = gwarp * 8; base < N_NODES; base += nwarps * 8) {
        // Load 8 node rows transposed into xsh[k][r].
        int r = lane >> 2;
        #pragma unroll
        for (int i = 0; i < 8; i++) {
            int c = (lane & 3) + 4 * i;
            float4 v = xa[(base + r) * 32 + c];
            float vv[4] = {v.x, v.y, v.z, v.w};
            #pragma unroll
            for (int j = 0; j < 4; j++)
                xsh[wl][(4 * c + j) * 8 + r] = vv[j];
        }
        __syncwarp();

        unsigned long long a00 = 0ull, a01 = 0ull, a02 = 0ull, a03 = 0ull;
        unsigned long long a10 = 0ull, a11 = 0ull, a12 = 0ull, a13 = 0ull;

        #pragma unroll 4
        for (int k = 0; k < D_FEAT; k++) {
            float wa = g_Wt[k * 64 + lane];
            float wb = g_Wt[k * 64 + 32 + (lane & 7)];
            unsigned long long wa2, wb2;
            PACK2(wa2, wa);
            PACK2(wb2, wb);
            ulonglong2 x01 = *(const ulonglong2*)&xsh[wl][k * 8];      // n0..3
            ulonglong2 x23 = *(const ulonglong2*)&xsh[wl][k * 8 + 4];  // n4..7
            FMA_F32X2(a00, wa2, x01.x); FMA_F32X2(a01, wa2, x01.y);
            FMA_F32X2(a02, wa2, x23.x); FMA_F32X2(a03, wa2, x23.y);
            FMA_F32X2(a10, wb2, x01.x); FMA_F32X2(a11, wb2, x01.y);
            FMA_F32X2(a12, wb2, x23.x); FMA_F32X2(a13, wb2, x23.y);
        }

        unsigned long long p0[4] = {a00, a01, a02, a03};
        unsigned long long p1[4] = {a10, a11, a12, a13};
        #pragma unroll
        for (int rr = 0; rr < 8; rr++) {
            float l0a, l0b, l1a, l1b;
            UNPACK2(l0a, l0b, p0[rr >> 1]);
            UNPACK2(l1a, l1b, p1[rr >> 1]);
            float y0 = (rr & 1) ? l0b : l0a;     // class = lane
            float y1 = (rr & 1) ? l1b : l1a;     // class = 32 + (lane&7)
            int node = base + rr;
            float dv = g_dinv[node];
            g_u[node * N_CLASSES + lane] = y0 * dv;
            if (lane < 8)
                g_u[node * N_CLASSES + 32 + lane] = y1 * dv;
        }
        __syncwarp();
    }
}

// ---- agg round 1 (40-dim): u2 = dinv^2 * ( u[w] + sum u[s] ) --------------
// Warp per node; lane holds class=lane, lanes 0-7 also class=32+lane.
// Gather = 160 B/row (5 sectors). 4-way unroll -> 8 loads in flight.
__global__ void k_aggA() {
    int w    = (blockIdx.x * blockDim.x + threadIdx.x) >> 5;
    int lane = threadIdx.x & 31;
    if (w >= N_NODES) return;
    int r0 = g_rowstart[w];
    int r1 = r0 + g_deg[w];
    bool hi = lane < 8;

    float a0 = g_u[w * N_CLASSES + lane];
    float a1 = hi ? g_u[w * N_CLASSES + 32 + lane] : 0.0f;

    int e = r0;
    for (; e + 4 <= r1; e += 4) {
        int i0 = g_csr[e],     i1 = g_csr[e + 1];
        int i2 = g_csr[e + 2], i3 = g_csr[e + 3];
        float v0 = g_u[i0 * N_CLASSES + lane];
        float v1 = g_u[i1 * N_CLASSES + lane];
        float v2 = g_u[i2 * N_CLASSES + lane];
        float v3 = g_u[i3 * N_CLASSES + lane];
        float u0 = hi ? g_u[i0 * N_CLASSES + 32 + lane] : 0.0f;
        float u1 = hi ? g_u[i1 * N_CLASSES + 32 + lane] : 0.0f;
        float u2 = hi ? g_u[i2 * N_CLASSES + 32 + lane] : 0.0f;
        float u3 = hi ? g_u[i3 * N_CLASSES + 32 + lane] : 0.0f;
        a0 += (v0 + v1) + (v2 + v3);
        a1 += (u0 + u1) + (u2 + u3);
    }
    for (; e < r1; e++) {
        int i0 = g_csr[e];
        a0 += g_u[i0 * N_CLASSES + lane];
        a1 += hi ? g_u[i0 * N_CLASSES + 32 + lane] : 0.0f;
    }
    float dv = g_dinv[w];
    float sc = dv * dv;
    g_u2[w * N_CLASSES + lane] = a0 * sc;
    if (hi) g_u2[w * N_CLASSES + 32 + lane] = a1 * sc;
}

// ---- agg round 2 + bias + log_softmax + output ----------------------------
__global__ void k_aggB(const float* __restrict__ b,
                       float* __restrict__ out) {
    int w    = (blockIdx.x * blockDim.x + threadIdx.x) >> 5;
    int lane = threadIdx.x & 31;
    if (w >= N_NODES) return;
    int r0 = g_rowstart[w];
    int r1 = r0 + g_deg[w];
    bool hi = lane < 8;

    float a0 = g_u2[w * N_CLASSES + lane];
    float a1 = hi ? g_u2[w * N_CLASSES + 32 + lane] : 0.0f;

    int e = r0;
    for (; e + 4 <= r1; e += 4) {
        int i0 = g_csr[e],     i1 = g_csr[e + 1];
        int i2 = g_csr[e + 2], i3 = g_csr[e + 3];
        float v0 = g_u2[i0 * N_CLASSES + lane];
        float v1 = g_u2[i1 * N_CLASSES + lane];
        float v2 = g_u2[i2 * N_CLASSES + lane];
        float v3 = g_u2[i3 * N_CLASSES + lane];
        float u0 = hi ? g_u2[i0 * N_CLASSES + 32 + lane] : 0.0f;
        float u1 = hi ? g_u2[i1 * N_CLASSES + 32 + lane] : 0.0f;
        float u2 = hi ? g_u2[i2 * N_CLASSES + 32 + lane] : 0.0f;
        float u3 = hi ? g_u2[i3 * N_CLASSES + 32 + lane] : 0.0f;
        a0 += (v0 + v1) + (v2 + v3);
        a1 += (u0 + u1) + (u2 + u3);
    }
    for (; e < r1; e++) {
        int i0 = g_csr[e];
        a0 += g_u2[i0 * N_CLASSES + lane];
        a1 += hi ? g_u2[i0 * N_CLASSES + 32 + lane] : 0.0f;
    }

    float dv = g_dinv[w];
    float l0 = a0 * dv + b[lane];
    float l1 = hi ? (a1 * dv + b[32 + lane]) : -1e30f;

    // warp log-softmax over 40 classes
    float m = fmaxf(l0, l1);
    #pragma unroll
    for (int off = 16; off; off >>= 1)
        m = fmaxf(m, __shfl_xor_sync(0xffffffffu, m, off));
    float s = expf(l0 - m) + (hi ? expf(l1 - m) : 0.0f);
    #pragma unroll
    for (int off = 16; off; off >>= 1)
        s += __shfl_xor_sync(0xffffffffu, s, off);
    float ls = m + logf(s);

    out[w * N_CLASSES + lane] = l0 - ls;
    if (hi)
        out[w * N_CLASSES + 32 + lane] = l1 - ls;
}

extern "C" void kernel_launch(void* const* d_in, const int* in_sizes, int n_in,
                              void* d_out, int out_size) {
    const float* x  = (const float*)d_in[0];
    const int*   ei = (const int*)d_in[1];   // dtype resolved on device (g_fmt)
    const float* W  = (const float*)d_in[2];
    const float* b  = (const float*)d_in[3];
    float* out = (float*)d_out;

    const int T = 256;
    const int nodeBlocks = (N_NODES + T - 1) / T;                 // 391
    const int edgeBlocks = (N_EDGES + T - 1) / T;                 // 2344
    const int aggBlocks  = (N_NODES * 32 + T - 1) / T;            // 12500

    k_init       <<<nodeBlocks, T>>>(W);
    k_probe      <<<edgeBlocks, T>>>(ei);
    k_count      <<<edgeBlocks, T>>>(ei);
    k_block_scan <<<NB_SCAN,    T>>>();
    k_scan_sums  <<<1,        512>>>();
    k_finalize   <<<nodeBlocks, T>>>();
    k_bin        <<<edgeBlocks, T>>>(ei);
    k_gemm       <<<1184,       T>>>((const float4*)x);
    k_aggA       <<<aggBlocks,  T>>>();
    k_aggB       <<<aggBlocks,  T>>>(b, out);
}